// round 7
// baseline (speedup 1.0000x reference)
#include <cuda_runtime.h>
#include <math.h>

#define NSPIN 256
#define FDIM  64
#define BATCH 64
#define NITER 40
#define TOLF  1e-4f
#define JS_STRIDE 260      // [128][260] floats: conflict-free LDS
#define AS_STRIDE 68       // [256][68] floats

// -------------------- device scratch (no runtime allocation) --------------------
__device__ float g_J[NSPIN * NSPIN];
__device__ float g_B2[NSPIN * NSPIN];                   // J^2 (epilogue target only)
__device__ float g_U1[BATCH * NSPIN * FDIM];            // J h
__device__ float g_U2[BATCH * NSPIN * FDIM];            // J^2 h
__device__ float g_pAA_h[BATCH][2];                     // s=0: ||h||^2, s=1: ||u1||^2
__device__ float g_pAC_h[BATCH][2][2];                  // s=0: <h,u1>, s=1: <u1,u2>
__device__ float g_pCC_h[BATCH][2];                     // ||u2||^2 partials
__device__ float g_pAA_t[4];                            // ||J||_F^2 = tr(J^2) partials
__device__ float g_pAC_t[2][4];                         // tr(J^3) partials
__device__ float g_pCC_t[2][4];                         // tr(J^4) partials
__device__ unsigned g_done;                             // zero-init; wraps each run

#define VL(x) (*(volatile float*)&(x))

// -------------------- helpers --------------------
__device__ __forceinline__ unsigned long long dup2(float a) {
    unsigned long long r;
    asm("mov.b64 %0, {%1, %1};" : "=l"(r) : "f"(a));
    return r;
}
__device__ __forceinline__ void fma2(unsigned long long& acc, unsigned long long a,
                                     unsigned long long b) {
    asm("fma.rn.f32x2 %0, %1, %2, %3;" : "=l"(acc) : "l"(a), "l"(b), "l"(acc));
}
__device__ __forceinline__ float lo32(unsigned long long v) {
    return __uint_as_float((unsigned)(v & 0xffffffffull));
}
__device__ __forceinline__ float hi32(unsigned long long v) {
    return __uint_as_float((unsigned)(v >> 32));
}

// block reduce for 512 threads (16 warps)
__device__ __forceinline__ float blockReduceSum(float v, float* scratch) {
    #pragma unroll
    for (int o = 16; o > 0; o >>= 1) v += __shfl_down_sync(0xffffffffu, v, o);
    int lane = threadIdx.x & 31, w = threadIdx.x >> 5;
    if (lane == 0) scratch[w] = v;
    __syncthreads();
    float r = 0.f;
    if (w == 0) {
        r = (lane < 16) ? scratch[lane] : 0.f;
        #pragma unroll
        for (int o = 8; o > 0; o >>= 1) r += __shfl_down_sync(0xffffffffu, r, o);
    }
    __syncthreads();
    return r;   // valid in thread 0
}

// -------------------- fp32 Newton + phi + afe tail (runs in last block) --------
__device__ void newton_tail(int b, float* out, int out_size) {
    float m0 = VL(g_pAA_h[b][0]);
    float m1 = VL(g_pAC_h[b][0][0]) + VL(g_pAC_h[b][0][1]);
    float m2 = VL(g_pAA_h[b][1]);
    float m3 = VL(g_pAC_h[b][1][0]) + VL(g_pAC_h[b][1][1]);
    float m4 = VL(g_pCC_h[b][0]) + VL(g_pCC_h[b][1]);

    float tp2 = 0.f, tp3 = 0.f, tp4 = 0.f;
    #pragma unroll
    for (int q = 0; q < 4; q++) tp2 += VL(g_pAA_t[q]);
    #pragma unroll
    for (int r = 0; r < 2; r++)
        #pragma unroll
        for (int q = 0; q < 4; q++) { tp3 += VL(g_pAC_t[r][q]); tp4 += VL(g_pCC_t[r][q]); }

    // folded Horner coefficients (tp0=256, tp1=0)
    const float cSa2 = tp2,        cSa3 = tp3,        cSa4 = tp4;
    const float cSb0 = 256.f,      cSb2 = 3.f * tp2,  cSb3 = 4.f * tp3, cSb4 = 5.f * tp4;
    const float cQb0 = m0, cQb1 = 2.f*m1, cQb2 = 3.f*m2, cQb3 = 4.f*m3, cQb4 = 5.f*m4;
    const float cQc0 = m0, cQc1 = 3.f*m1, cQc2 = 6.f*m2, cQc3 = 10.f*m3, cQc4 = 15.f*m4;

    float t = 1.0f;
    for (int it = 0; it < NITER; ++it) {
        float xv = 1.0f / t;
        float Sa = (((cSa4 * xv + cSa3) * xv + cSa2) * xv) * xv + 256.f;
        float Sb = (((cSb4 * xv + cSb3) * xv + cSb2) * xv) * xv + cSb0;
        float Qb = (((cQb4 * xv + cQb3) * xv + cQb2) * xv + cQb1) * xv + cQb0;
        float Qc = (((cQc4 * xv + cQc3) * xv + cQc2) * xv + cQc1) * xv + cQc0;
        float s1 = xv * Sa;
        float s2 = xv * xv * Sb;
        float q2 = xv * xv * Qb;
        float q3 = xv * xv * xv * Qc;
        float g  = 256.f - 0.5f * s1 - q2 * (1.f / 256.f);
        if (fabsf(g) <= TOLF) break;      // reference's update is 0 from here on
        float gp = 0.5f * s2 + q3 * (1.f / 128.f);
        t -= g / gp;
    }

    float xv = 1.0f / t;
    float Qa = ((((m4 * xv + m3) * xv + m2) * xv + m1) * xv + m0);
    float q1 = xv * Qa;
    float lds = ((tp4 * 0.25f * xv + tp3 * (1.f / 3.f)) * xv + tp2 * 0.5f) * xv * xv;
    float logdet = 256.f * __logf(t) - lds;
    float phi = 256.f * t - 0.5f * logdet + q1 * (1.f / 256.f);
    float afe = -(0.57236494292f + phi * (1.f / 256.f));   // 0.5*log(pi) + phi/N

    out[b] = afe;
    if (out_size >= 2 * BATCH) out[BATCH + b] = t;
}

// -------------------- the gemm step (2 launches total) --------------------------
// s==0: grid=128. H-part only: u1[b] = J @ h[b]; blocks 0,1 also publish g_J.
//       J symmetrization fused into staging.
// s==1: grid=136. u2[b] = J @ u1[b]; blocks 128..135: B2 = J @ J.
//       Last block to finish runs fp32 Newton + writes outputs.
__global__ void __launch_bounds__(512, 1)
gemm_step(const float* __restrict__ x, const float* __restrict__ Jr,
          float* __restrict__ out, int out_size, int s) {
    extern __shared__ float sh[];
    float* Js = sh;                               // [128][JS_STRIDE]
    float* As = sh + 128 * JS_STRIDE;             // [256][AS_STRIDE]

    const int bid = blockIdx.x;
    const int tid = threadIdx.x;

    bool isH;
    int b = 0, rt, ct, ncols, col0;
    const float* A;
    float* C;

    if (bid < 128) {
        isH = true;
        b = bid >> 1; rt = bid & 1; ct = 0;
        ncols = FDIM; col0 = 0;
        A = ((s == 0) ? x : g_U1) + (size_t)b * NSPIN * FDIM;
        C = ((s == 0) ? g_U1 : g_U2) + (size_t)b * NSPIN * FDIM;
    } else {
        isH = false;
        int t = bid - 128;
        rt = t >> 2; ct = t & 3;
        ncols = NSPIN; col0 = ct * 64;
        A = g_J;
        C = g_B2;
    }
    const int row0 = rt * 128;

    // stage J row-block [128][256]
    if (s == 0) {
        // fused symmetrize + traceless from raw J; blocks 0,1 publish g_J
        for (int idx = tid; idx < 128 * 64; idx += 512) {
            int r = idx >> 6, k4 = (idx & 63) * 4;
            int gr = row0 + r;
            float4 v = *(const float4*)&Jr[gr * NSPIN + k4];
            float t0 = Jr[(k4 + 0) * NSPIN + gr];
            float t1 = Jr[(k4 + 1) * NSPIN + gr];
            float t2 = Jr[(k4 + 2) * NSPIN + gr];
            float t3 = Jr[(k4 + 3) * NSPIN + gr];
            v.x = (k4 + 0 == gr) ? 0.f : 0.5f * (v.x + t0);
            v.y = (k4 + 1 == gr) ? 0.f : 0.5f * (v.y + t1);
            v.z = (k4 + 2 == gr) ? 0.f : 0.5f * (v.z + t2);
            v.w = (k4 + 3 == gr) ? 0.f : 0.5f * (v.w + t3);
            *(float4*)&Js[r * JS_STRIDE + k4] = v;
            if (bid < 2) *(float4*)&g_J[gr * NSPIN + k4] = v;
        }
    } else {
        for (int idx = tid; idx < 128 * 64; idx += 512) {
            int r = idx >> 6, k4 = (idx & 63) * 4;
            *(float4*)&Js[r * JS_STRIDE + k4] =
                *(const float4*)&g_J[(row0 + r) * NSPIN + k4];
        }
    }
    // stage A col-slice [256][64]
    for (int idx = tid; idx < 256 * 16; idx += 512) {
        int k = idx >> 4, c4 = idx & 15;
        *(float4*)&As[k * AS_STRIDE + c4 * 4] =
            *(const float4*)&A[(size_t)k * ncols + col0 + c4 * 4];
    }
    __syncthreads();

    // thread map: ty = tid&63 (row), tx = tid>>6 (col group of 8)
    const int ty = tid & 63;
    const int tx = tid >> 6;

    unsigned long long acc[2][4];
    #pragma unroll
    for (int i = 0; i < 2; i++)
        #pragma unroll
        for (int j = 0; j < 4; j++) acc[i][j] = 0ull;

    const float* jr0 = &Js[ty * JS_STRIDE];
    const float* jr1 = &Js[(ty + 64) * JS_STRIDE];
    const float* bcol = &As[tx * 8];

    #pragma unroll 2
    for (int kk = 0; kk < 256; kk += 4) {
        float4 ja = *(const float4*)&jr0[kk];
        float4 jb = *(const float4*)&jr1[kk];
        #pragma unroll
        for (int u = 0; u < 4; ++u) {
            ulonglong2 b0 = *(const ulonglong2*)&bcol[(kk + u) * AS_STRIDE];
            ulonglong2 b1 = *(const ulonglong2*)&bcol[(kk + u) * AS_STRIDE + 4];
            float jav = (u == 0) ? ja.x : (u == 1) ? ja.y : (u == 2) ? ja.z : ja.w;
            float jbv = (u == 0) ? jb.x : (u == 1) ? jb.y : (u == 2) ? jb.z : jb.w;
            unsigned long long a0 = dup2(jav);
            unsigned long long a1 = dup2(jbv);
            fma2(acc[0][0], a0, b0.x); fma2(acc[0][1], a0, b0.y);
            fma2(acc[0][2], a0, b1.x); fma2(acc[0][3], a0, b1.y);
            fma2(acc[1][0], a1, b0.x); fma2(acc[1][1], a1, b0.y);
            fma2(acc[1][2], a1, b1.x); fma2(acc[1][3], a1, b1.y);
        }
    }

    // epilogue: store C, fused dots <A,C>, (s==1) <C,C>
    float ac = 0.f, cc = 0.f;
    #pragma unroll
    for (int i = 0; i < 2; i++) {
        int r = row0 + ty + 64 * i;     // global row index (= k-index of A)
        float c0 = lo32(acc[i][0]), c1 = hi32(acc[i][0]);
        float c2 = lo32(acc[i][1]), c3 = hi32(acc[i][1]);
        float c4 = lo32(acc[i][2]), c5 = hi32(acc[i][2]);
        float c6 = lo32(acc[i][3]), c7 = hi32(acc[i][3]);
        float* cp = &C[(size_t)r * ncols + col0 + tx * 8];
        *(float4*)cp       = make_float4(c0, c1, c2, c3);
        *(float4*)(cp + 4) = make_float4(c4, c5, c6, c7);
        const float* arow = &As[r * AS_STRIDE + tx * 8];
        ac += c0 * arow[0] + c1 * arow[1] + c2 * arow[2] + c3 * arow[3]
            + c4 * arow[4] + c5 * arow[5] + c6 * arow[6] + c7 * arow[7];
        if (s) cc += c0 * c0 + c1 * c1 + c2 * c2 + c3 * c3
                   + c4 * c4 + c5 * c5 + c6 * c6 + c7 * c7;
    }
    // <A,A> over the full staged slice (rt==0 blocks only)
    float aa = 0.f;
    if (rt == 0) {
        for (int idx = tid; idx < 256 * 64; idx += 512) {
            int k = idx >> 6, c = idx & 63;
            float v = As[k * AS_STRIDE + c];
            aa += v * v;
        }
    }

    __syncthreads();                 // Js region now reusable as scratch
    float* scratch = sh;

    float acr = blockReduceSum(ac, scratch);
    if (tid == 0) {
        if (isH) g_pAC_h[b][s][rt] = acr;
        else     g_pAC_t[rt][ct] = acr;
    }
    float aar = blockReduceSum(aa, scratch);
    if (tid == 0 && rt == 0) {
        if (isH) g_pAA_h[b][s] = aar;
        else     g_pAA_t[ct] = aar;
    }
    if (s) {
        float ccr = blockReduceSum(cc, scratch);
        if (tid == 0) {
            if (isH) g_pCC_h[b][rt] = ccr;
            else     g_pCC_t[rt][ct] = ccr;
        }

        // ---- last-block-done: run fp32 Newton inline ----
        __shared__ unsigned islast;
        if (tid == 0) islast = 0u;
        __syncthreads();
        __threadfence();
        if (tid == 0) {
            unsigned old = atomicInc(&g_done, 136 - 1);
            if (old == 136 - 1) islast = 1u;
        }
        __syncthreads();
        if (islast) {
            __threadfence();
            if (tid < BATCH) newton_tail(tid, out, out_size);
        }
    }
}

// -------------------- launch --------------------
extern "C" void kernel_launch(void* const* d_in, const int* in_sizes, int n_in,
                              void* d_out, int out_size) {
    const float* x  = (const float*)d_in[0];   // (64, 256, 64)
    const float* Jr = (const float*)d_in[1];   // (256, 256)
    float* out = (float*)d_out;

    size_t shmem = (size_t)(128 * JS_STRIDE + 256 * AS_STRIDE) * sizeof(float);
    cudaFuncSetAttribute(gemm_step, cudaFuncAttributeMaxDynamicSharedMemorySize,
                         (int)shmem);

    gemm_step<<<128, 512, shmem>>>(x, Jr, out, out_size, 0);  // u1 = J h  (+m0,m1; J built)
    gemm_step<<<136, 512, shmem>>>(x, Jr, out, out_size, 1);  // u2, B2, Newton tail
}

// round 8
// speedup vs baseline: 1.5894x; 1.5894x over previous
#include <cuda_runtime.h>
#include <math.h>

#define NSPIN 256
#define FDIM  64
#define BATCH 64
#define NITER 40
#define TOLF  1e-4f
#define JS_STRIDE 260      // [128][260] floats: conflict-free LDS
#define AS_STRIDE 68       // [256][68] floats
#define NBLK   136u

// -------------------- device scratch (no runtime allocation) --------------------
__device__ float g_J[NSPIN * NSPIN];
__device__ float g_U1[BATCH * NSPIN * FDIM];            // J h (phase1 -> phase2 handoff)
__device__ float g_pAA_h[BATCH][2];                     // ||h||^2, ||u1||^2
__device__ float g_pAC_h[BATCH][2][2];                  // <h,u1>, <u1,u2> (2 row tiles)
__device__ float g_pCC_h[BATCH][2];                     // ||u2||^2 partials
__device__ float g_pAA_t[4];                            // tr(J^2) partials (4 col tiles)
__device__ float g_pAC_t[2][4];                         // tr(J^3) partials
__device__ float g_pCC_t[2][4];                         // tr(J^4) partials
__device__ unsigned g_bar;                              // monotonic ticket counter

#define VL(x) (*(volatile float*)&(x))

// -------------------- helpers --------------------
__device__ __forceinline__ unsigned long long dup2(float a) {
    unsigned long long r;
    asm("mov.b64 %0, {%1, %1};" : "=l"(r) : "f"(a));
    return r;
}
__device__ __forceinline__ void fma2(unsigned long long& acc, unsigned long long a,
                                     unsigned long long b) {
    asm("fma.rn.f32x2 %0, %1, %2, %3;" : "=l"(acc) : "l"(a), "l"(b), "l"(acc));
}
__device__ __forceinline__ float lo32(unsigned long long v) {
    return __uint_as_float((unsigned)(v & 0xffffffffull));
}
__device__ __forceinline__ float hi32(unsigned long long v) {
    return __uint_as_float((unsigned)(v >> 32));
}

// grid-wide barrier: monotonic tickets, replay-safe (no reset needed).
// Valid because all 136 blocks are co-resident (1 block/SM, 136 <= 148 SMs).
__device__ __forceinline__ void grid_barrier() {
    __threadfence();               // each thread publishes its own stores
    __syncthreads();
    if (threadIdx.x == 0) {
        unsigned old = atomicAdd(&g_bar, 1u);
        unsigned target = old - (old % NBLK) + NBLK;
        while ((int)(*(volatile unsigned*)&g_bar - target) < 0) __nanosleep(64);
    }
    __syncthreads();
}

// block reduce for 512 threads (16 warps) using a dedicated static scratch
__device__ __forceinline__ float blockReduceSum(float v, float* scratch) {
    #pragma unroll
    for (int o = 16; o > 0; o >>= 1) v += __shfl_down_sync(0xffffffffu, v, o);
    int lane = threadIdx.x & 31, w = threadIdx.x >> 5;
    if (lane == 0) scratch[w] = v;
    __syncthreads();
    float r = 0.f;
    if (w == 0) {
        r = (lane < 16) ? scratch[lane] : 0.f;
        #pragma unroll
        for (int o = 8; o > 0; o >>= 1) r += __shfl_down_sync(0xffffffffu, r, o);
    }
    __syncthreads();
    return r;   // valid in thread 0
}

// -------------------- inner gemm: acc[2][4] over staged Js/As ------------------
__device__ __forceinline__ void gemm_core(const float* jr0, const float* jr1,
                                          const float* bcol,
                                          unsigned long long acc[2][4]) {
    #pragma unroll
    for (int i = 0; i < 2; i++)
        #pragma unroll
        for (int j = 0; j < 4; j++) acc[i][j] = 0ull;
    #pragma unroll 2
    for (int kk = 0; kk < 256; kk += 4) {
        float4 ja = *(const float4*)&jr0[kk];
        float4 jb = *(const float4*)&jr1[kk];
        #pragma unroll
        for (int u = 0; u < 4; ++u) {
            ulonglong2 b0 = *(const ulonglong2*)&bcol[(kk + u) * AS_STRIDE];
            ulonglong2 b1 = *(const ulonglong2*)&bcol[(kk + u) * AS_STRIDE + 4];
            float jav = (u == 0) ? ja.x : (u == 1) ? ja.y : (u == 2) ? ja.z : ja.w;
            float jbv = (u == 0) ? jb.x : (u == 1) ? jb.y : (u == 2) ? jb.z : jb.w;
            unsigned long long a0 = dup2(jav);
            unsigned long long a1 = dup2(jbv);
            fma2(acc[0][0], a0, b0.x); fma2(acc[0][1], a0, b0.y);
            fma2(acc[0][2], a0, b1.x); fma2(acc[0][3], a0, b1.y);
            fma2(acc[1][0], a1, b0.x); fma2(acc[1][1], a1, b0.y);
            fma2(acc[1][2], a1, b1.x); fma2(acc[1][3], a1, b1.y);
        }
    }
}

// -------------------- fp32 Newton + phi + afe tail (last arrival) --------------
__device__ void newton_tail(int b, float* out, int out_size) {
    float m0 = VL(g_pAA_h[b][0]);
    float m1 = VL(g_pAC_h[b][0][0]) + VL(g_pAC_h[b][0][1]);
    float m2 = VL(g_pAA_h[b][1]);
    float m3 = VL(g_pAC_h[b][1][0]) + VL(g_pAC_h[b][1][1]);
    float m4 = VL(g_pCC_h[b][0]) + VL(g_pCC_h[b][1]);

    float tp2 = 0.f, tp3 = 0.f, tp4 = 0.f;
    #pragma unroll
    for (int q = 0; q < 4; q++) tp2 += VL(g_pAA_t[q]);
    #pragma unroll
    for (int r = 0; r < 2; r++)
        #pragma unroll
        for (int q = 0; q < 4; q++) { tp3 += VL(g_pAC_t[r][q]); tp4 += VL(g_pCC_t[r][q]); }

    const float cSb2 = 3.f * tp2, cSb3 = 4.f * tp3, cSb4 = 5.f * tp4;
    const float cQb0 = m0, cQb1 = 2.f*m1, cQb2 = 3.f*m2, cQb3 = 4.f*m3, cQb4 = 5.f*m4;
    const float cQc0 = m0, cQc1 = 3.f*m1, cQc2 = 6.f*m2, cQc3 = 10.f*m3, cQc4 = 15.f*m4;

    float t = 1.0f;
    for (int it = 0; it < NITER; ++it) {
        float xv = 1.0f / t;
        float Sa = (((tp4 * xv + tp3) * xv + tp2) * xv) * xv + 256.f;
        float Sb = (((cSb4 * xv + cSb3) * xv + cSb2) * xv) * xv + 256.f;
        float Qb = (((cQb4 * xv + cQb3) * xv + cQb2) * xv + cQb1) * xv + cQb0;
        float Qc = (((cQc4 * xv + cQc3) * xv + cQc2) * xv + cQc1) * xv + cQc0;
        float s1 = xv * Sa;
        float s2 = xv * xv * Sb;
        float q2 = xv * xv * Qb;
        float q3 = xv * xv * xv * Qc;
        float g  = 256.f - 0.5f * s1 - q2 * (1.f / 256.f);
        if (fabsf(g) <= TOLF) break;      // reference's update is 0 from here on
        float gp = 0.5f * s2 + q3 * (1.f / 128.f);
        t -= g / gp;
    }

    float xv = 1.0f / t;
    float Qa = ((((m4 * xv + m3) * xv + m2) * xv + m1) * xv + m0);
    float q1 = xv * Qa;
    float lds = ((tp4 * 0.25f * xv + tp3 * (1.f / 3.f)) * xv + tp2 * 0.5f) * xv * xv;
    float logdet = 256.f * __logf(t) - lds;
    float phi = 256.f * t - 0.5f * logdet + q1 * (1.f / 256.f);
    float afe = -(0.57236494292f + phi * (1.f / 256.f));   // 0.5*log(pi) + phi/N

    out[b] = afe;
    if (out_size >= 2 * BATCH) out[BATCH + b] = t;
}

// -------------------- the single fused kernel ----------------------------------
// Blocks 0..127 (H): b = bid>>1, rt = bid&1.
//   phase1: u1[b] = J @ h[b] (+ ||h||^2, <h,u1>)
//   phase2: u2 = J @ u1[b] in regs only (+ ||u1||^2, <u1,u2>, ||u2||^2)
// Blocks 128..135 (T): rt = t>>2, ct = t&3.
//   phase1: stage J col-slice, tr(J^2) partials
//   phase2: J@J tile in regs only -> tr(J^3), tr(J^4) partials
__global__ void __launch_bounds__(512, 1)
fused_kernel(const float* __restrict__ x, const float* __restrict__ Jr,
             float* __restrict__ out, int out_size) {
    extern __shared__ float sh[];
    float* Js = sh;                               // [128][JS_STRIDE] — persists all phases
    float* As = sh + 128 * JS_STRIDE;             // [256][AS_STRIDE]
    __shared__ float scratch[16];
    __shared__ unsigned islast;

    const int bid = blockIdx.x;
    const int tid = threadIdx.x;
    const bool isH = (bid < 128);

    int b = 0, rt, ct;
    if (isH) { b = bid >> 1; rt = bid & 1; ct = 0; }
    else     { int t = bid - 128; rt = t >> 2; ct = t & 3; }
    const int row0 = rt * 128;
    const int col0 = ct * 64;

    // ---- phase 0: build J once, cooperatively (2 rows per H block) ----
    if (isH) {
        int r = bid * 2 + (tid >> 8);
        int j = tid & 255;
        float v = (r == j) ? 0.f : 0.5f * (Jr[r * NSPIN + j] + Jr[j * NSPIN + r]);
        g_J[r * NSPIN + j] = v;
    }
    grid_barrier();

    // ---- stage Js once (valid for both phases; rt fixed per block) ----
    for (int idx = tid; idx < 128 * 64; idx += 512) {
        int r = idx >> 6, k4 = (idx & 63) * 4;
        *(float4*)&Js[r * JS_STRIDE + k4] =
            *(const float4*)&g_J[(row0 + r) * NSPIN + k4];
    }
    // ---- stage As for phase 1 ----
    if (isH) {
        const float* A = x + (size_t)b * NSPIN * FDIM;
        for (int idx = tid; idx < 256 * 16; idx += 512) {
            int k = idx >> 4, c4 = idx & 15;
            *(float4*)&As[k * AS_STRIDE + c4 * 4] =
                *(const float4*)&A[(size_t)k * FDIM + c4 * 4];
        }
    } else {
        for (int idx = tid; idx < 256 * 16; idx += 512) {
            int k = idx >> 4, c4 = idx & 15;
            *(float4*)&As[k * AS_STRIDE + c4 * 4] =
                *(const float4*)&g_J[(size_t)k * NSPIN + col0 + c4 * 4];
        }
    }
    __syncthreads();

    const int ty = tid & 63;
    const int tx = tid >> 6;
    const float* jr0 = &Js[ty * JS_STRIDE];
    const float* jr1 = &Js[(ty + 64) * JS_STRIDE];
    const float* bcol = &As[tx * 8];

    // ---- phase 1 ----
    if (isH) {
        unsigned long long acc[2][4];
        gemm_core(jr0, jr1, bcol, acc);
        float* C = g_U1 + (size_t)b * NSPIN * FDIM;
        float ac = 0.f;
        #pragma unroll
        for (int i = 0; i < 2; i++) {
            int r = row0 + ty + 64 * i;
            float c0 = lo32(acc[i][0]), c1 = hi32(acc[i][0]);
            float c2 = lo32(acc[i][1]), c3 = hi32(acc[i][1]);
            float c4 = lo32(acc[i][2]), c5 = hi32(acc[i][2]);
            float c6 = lo32(acc[i][3]), c7 = hi32(acc[i][3]);
            float* cp = &C[(size_t)r * FDIM + tx * 8];
            *(float4*)cp       = make_float4(c0, c1, c2, c3);
            *(float4*)(cp + 4) = make_float4(c4, c5, c6, c7);
            const float* arow = &As[r * AS_STRIDE + tx * 8];
            ac += c0 * arow[0] + c1 * arow[1] + c2 * arow[2] + c3 * arow[3]
                + c4 * arow[4] + c5 * arow[5] + c6 * arow[6] + c7 * arow[7];
        }
        float aa = 0.f;
        if (rt == 0) {
            for (int idx = tid; idx < 256 * 64; idx += 512) {
                int k = idx >> 6, c = idx & 63;
                float v = As[k * AS_STRIDE + c];
                aa += v * v;
            }
        }
        float acr = blockReduceSum(ac, scratch);
        if (tid == 0) g_pAC_h[b][0][rt] = acr;
        float aar = blockReduceSum(aa, scratch);
        if (tid == 0 && rt == 0) g_pAA_h[b][0] = aar;
    } else {
        // tr(J^2) partials from staged col-slice (rt==0 blocks only)
        if (rt == 0) {
            float aa = 0.f;
            for (int idx = tid; idx < 256 * 64; idx += 512) {
                int k = idx >> 6, c = idx & 63;
                float v = As[k * AS_STRIDE + c];
                aa += v * v;
            }
            float aar = blockReduceSum(aa, scratch);
            if (tid == 0) g_pAA_t[ct] = aar;
        }
    }
    grid_barrier();

    // ---- phase 2 ----
    float ac = 0.f, cc = 0.f, aa = 0.f;
    if (isH) {
        // restage As = u1[b]
        const float* A = g_U1 + (size_t)b * NSPIN * FDIM;
        for (int idx = tid; idx < 256 * 16; idx += 512) {
            int k = idx >> 4, c4 = idx & 15;
            *(float4*)&As[k * AS_STRIDE + c4 * 4] =
                *(const float4*)&A[(size_t)k * FDIM + c4 * 4];
        }
        __syncthreads();
    }
    {
        unsigned long long acc[2][4];
        gemm_core(jr0, jr1, bcol, acc);
        #pragma unroll
        for (int i = 0; i < 2; i++) {
            int r = row0 + ty + 64 * i;
            float c0 = lo32(acc[i][0]), c1 = hi32(acc[i][0]);
            float c2 = lo32(acc[i][1]), c3 = hi32(acc[i][1]);
            float c4 = lo32(acc[i][2]), c5 = hi32(acc[i][2]);
            float c6 = lo32(acc[i][3]), c7 = hi32(acc[i][3]);
            const float* arow = &As[r * AS_STRIDE + tx * 8];
            ac += c0 * arow[0] + c1 * arow[1] + c2 * arow[2] + c3 * arow[3]
                + c4 * arow[4] + c5 * arow[5] + c6 * arow[6] + c7 * arow[7];
            cc += c0 * c0 + c1 * c1 + c2 * c2 + c3 * c3
                + c4 * c4 + c5 * c5 + c6 * c6 + c7 * c7;
        }
        if (isH && rt == 0) {
            for (int idx = tid; idx < 256 * 64; idx += 512) {
                int k = idx >> 6, c = idx & 63;
                float v = As[k * AS_STRIDE + c];
                aa += v * v;
            }
        }
    }
    float acr = blockReduceSum(ac, scratch);
    if (tid == 0) {
        if (isH) g_pAC_h[b][1][rt] = acr;
        else     g_pAC_t[rt][ct] = acr;
    }
    float ccr = blockReduceSum(cc, scratch);
    if (tid == 0) {
        if (isH) g_pCC_h[b][rt] = ccr;
        else     g_pCC_t[rt][ct] = ccr;
    }
    if (isH && rt == 0) {
        float aar = blockReduceSum(aa, scratch);
        if (tid == 0) g_pAA_h[b][1] = aar;
    }

    // ---- final arrival: last block runs fp32 Newton tail ----
    if (tid == 0) {
        islast = 0u;
        __threadfence();
        unsigned old = atomicAdd(&g_bar, 1u);
        if ((old % NBLK) == NBLK - 1u) islast = 1u;
    }
    __syncthreads();
    if (islast) {
        __threadfence();
        if (tid < BATCH) newton_tail(tid, out, out_size);
    }
}

// -------------------- launch --------------------
extern "C" void kernel_launch(void* const* d_in, const int* in_sizes, int n_in,
                              void* d_out, int out_size) {
    const float* x  = (const float*)d_in[0];   // (64, 256, 64)
    const float* Jr = (const float*)d_in[1];   // (256, 256)
    float* out = (float*)d_out;

    size_t shmem = (size_t)(128 * JS_STRIDE + 256 * AS_STRIDE) * sizeof(float);
    cudaFuncSetAttribute(fused_kernel, cudaFuncAttributeMaxDynamicSharedMemorySize,
                         (int)shmem);

    fused_kernel<<<NBLK, 512, shmem>>>(x, Jr, out, out_size);
}